// round 3
// baseline (speedup 1.0000x reference)
#include <cuda_runtime.h>

// Problem constants
#define NB   2          // batch N
#define KC   4          // classes K
#define NK   8          // N*K
#define HH   80
#define WW   80
#define DD   80
#define VOX  512000     // 80^3
#define B1   128        // blocks per n in sum pass
#define CHUNK 4000      // VOX / B1

// 11-tap unnormalized Gaussian, sigma=4:  g[i] = exp(-(i-5)^2/32)
__device__ __forceinline__ float gtap(int t) {
    const float g[11] = {
        0.45783335f, 0.60653066f, 0.75483960f, 0.88249690f, 0.96923321f,
        1.00000000f,
        0.96923321f, 0.88249690f, 0.75483960f, 0.60653066f, 0.45783335f };
    return g[t];
}

// Scratch (device globals; no allocation allowed)
__device__ float g_buf1[16 * VOX];   // after conv-D: [nk*2+ch][h][w][d]
__device__ float g_buf2[16 * VOX];   // after conv-W
__device__ float g_part1[NB * B1 * 8];
__device__ float g_mean[NK];
__device__ float g_partD[NK * WW * 2];

// ---------------- K1: per-block partial sums of lab and inp*lab ----------------
__global__ __launch_bounds__(256) void k_sums(const float* __restrict__ labels,
                                              const float* __restrict__ inputs) {
    int n = blockIdx.y;
    int b = blockIdx.x;
    int start = b * CHUNK;
    int end   = start + CHUNK;   // exact partition: 128*4000 = 512000

    float a[8];
    #pragma unroll
    for (int j = 0; j < 8; j++) a[j] = 0.f;

    const float* ip = inputs + (size_t)n * VOX;
    for (int v = start + threadIdx.x; v < end; v += blockDim.x) {
        float iv = ip[v];
        #pragma unroll
        for (int k = 0; k < 4; k++) {
            float lv = labels[(size_t)(n * 4 + k) * VOX + v];
            a[k]     += lv;
            a[4 + k] += iv * lv;
        }
    }
    // warp reduce
    #pragma unroll
    for (int o = 16; o > 0; o >>= 1)
        #pragma unroll
        for (int j = 0; j < 8; j++)
            a[j] += __shfl_down_sync(0xffffffffu, a[j], o);

    __shared__ float s[8][8];
    int wid = threadIdx.x >> 5, lid = threadIdx.x & 31;
    if (lid == 0)
        #pragma unroll
        for (int j = 0; j < 8; j++) s[wid][j] = a[j];
    __syncthreads();
    if (threadIdx.x < 8) {
        int j = threadIdx.x;
        float acc = 0.f;
        #pragma unroll
        for (int w = 0; w < 8; w++) acc += s[w][j];
        g_part1[(size_t)(n * B1 + b) * 8 + j] = acc;
    }
}

// ---------------- K2: finish means ----------------
__global__ __launch_bounds__(256) void k_means() {
    int wid = threadIdx.x >> 5, lid = threadIdx.x & 31;  // wid = nk
    int n = wid >> 2, k = wid & 3;
    float sp = 0.f, sip = 0.f;
    for (int b = lid; b < B1; b += 32) {
        const float* p = g_part1 + (size_t)(n * B1 + b) * 8;
        sp  += p[k];
        sip += p[4 + k];
    }
    #pragma unroll
    for (int o = 16; o > 0; o >>= 1) {
        sp  += __shfl_down_sync(0xffffffffu, sp, o);
        sip += __shfl_down_sync(0xffffffffu, sip, o);
    }
    if (lid == 0)
        g_mean[wid] = sip / (sp + 5.12f);   // 1e-5 * 512000
}

// ---------------- K3: weights + pw, conv along D ----------------
// grid = NK*HH blocks; block handles one (nk,h) plane of 80x80
__global__ __launch_bounds__(256) void k_convD(const float* __restrict__ labels,
                                               const float* __restrict__ inputs) {
    int bx = blockIdx.x;
    int nk = bx / HH, h = bx % HH;
    int n = nk >> 2;
    float m = g_mean[nk];

    __shared__ float ws[8][90];
    __shared__ float pws[8][90];

    const float* ipl = inputs + (size_t)n  * VOX + (size_t)h * (WW * DD);
    const float* lpl = labels + (size_t)nk * VOX + (size_t)h * (WW * DD);
    float* o_w  = g_buf1 + (size_t)(nk * 2 + 0) * VOX + (size_t)h * (WW * DD);
    float* o_pw = g_buf1 + (size_t)(nk * 2 + 1) * VOX + (size_t)h * (WW * DD);

    for (int r0 = 0; r0 < WW; r0 += 8) {
        // halo zeros: cols 0..4 and 85..89 of each of 8 rows
        for (int j = threadIdx.x; j < 80; j += blockDim.x) {
            int r = j / 10, p = j % 10;
            int c = (p < 5) ? p : (p + 80);
            ws[r][c] = 0.f; pws[r][c] = 0.f;
        }
        for (int i = threadIdx.x; i < 640; i += blockDim.x) {
            int r = i / 80, d = i % 80;
            int w = r0 + r;
            float iv = ipl[w * DD + d];
            float lv = lpl[w * DD + d];
            float t  = iv - m;
            float t2 = t * t;
            float wv = __expf(-t2 * t2);
            ws[r][d + 5]  = wv;
            pws[r][d + 5] = lv * wv;
        }
        __syncthreads();
        for (int i = threadIdx.x; i < 640; i += blockDim.x) {
            int r = i / 80, d = i % 80;
            int w = r0 + r;
            float aw = 0.f, apw = 0.f;
            #pragma unroll
            for (int t = 0; t < 11; t++) {
                float gt = gtap(t);
                aw  += gt * ws[r][d + t];
                apw += gt * pws[r][d + t];
            }
            o_w[w * DD + d]  = aw;
            o_pw[w * DD + d] = apw;
        }
        __syncthreads();
    }
}

// ---------------- K4: conv along W ----------------
// grid = 16*HH blocks; block handles one (vol,h) plane, staged in smem
__global__ __launch_bounds__(256) void k_convW() {
    int bx = blockIdx.x;
    int v  = bx / HH, h = bx % HH;
    __shared__ float pl[90 * 80];  // rows 0..4, 85..89 are zero halo

    const float* in = g_buf1 + (size_t)v * VOX + (size_t)h * (WW * DD);
    float*      out = g_buf2 + (size_t)v * VOX + (size_t)h * (WW * DD);

    for (int i = threadIdx.x; i < 800; i += blockDim.x) {
        int r = i / 80, d = i % 80;
        int row = (r < 5) ? r : (r + 80);
        pl[row * 80 + d] = 0.f;
    }
    for (int i = threadIdx.x; i < 6400; i += blockDim.x) {
        int w = i / 80, d = i % 80;
        pl[(w + 5) * 80 + d] = in[i];
    }
    __syncthreads();
    for (int i = threadIdx.x; i < 6400; i += blockDim.x) {
        int w = i / 80, d = i % 80;
        float acc = 0.f;
        #pragma unroll
        for (int t = 0; t < 11; t++)
            acc += gtap(t) * pl[(w + t) * 80 + d];
        out[i] = acc;
    }
}

// ---------------- K5: conv along H + fused label reduction ----------------
// grid = NK*WW blocks; block handles (nk, w): (h,d) plane per channel
__global__ __launch_bounds__(256) void k_convH(const float* __restrict__ labels) {
    int bx = blockIdx.x;
    int nk = bx / WW, w = bx % WW;
    __shared__ float pl[90 * 80];

    const float* lab = labels + (size_t)nk * VOX + (size_t)w * DD;  // (h,d): lab[h*6400+d]

    float num = 0.f, den = 0.f;
    for (int ch = 0; ch < 2; ch++) {
        const float* in = g_buf2 + (size_t)(nk * 2 + ch) * VOX + (size_t)w * DD;
        for (int i = threadIdx.x; i < 800; i += blockDim.x) {
            int r = i / 80, d = i % 80;
            int row = (r < 5) ? r : (r + 80);
            pl[row * 80 + d] = 0.f;
        }
        for (int i = threadIdx.x; i < 6400; i += blockDim.x) {
            int h = i / 80, d = i % 80;
            pl[(h + 5) * 80 + d] = in[(size_t)h * (WW * DD) + d];
        }
        __syncthreads();
        for (int i = threadIdx.x; i < 6400; i += blockDim.x) {
            int h = i / 80, d = i % 80;
            float acc = 0.f;
            #pragma unroll
            for (int t = 0; t < 11; t++)
                acc += gtap(t) * pl[(h + t) * 80 + d];
            float lv = lab[(size_t)h * (WW * DD) + d];
            if (ch == 0) den += lv * acc;
            else         num += lv * acc;
        }
        __syncthreads();
    }
    // block reduce num/den
    #pragma unroll
    for (int o = 16; o > 0; o >>= 1) {
        num += __shfl_down_sync(0xffffffffu, num, o);
        den += __shfl_down_sync(0xffffffffu, den, o);
    }
    __shared__ float sn[8], sd[8];
    int wid = threadIdx.x >> 5, lid = threadIdx.x & 31;
    if (lid == 0) { sn[wid] = num; sd[wid] = den; }
    __syncthreads();
    if (threadIdx.x == 0) {
        float tn = 0.f, td = 0.f;
        #pragma unroll
        for (int j = 0; j < 8; j++) { tn += sn[j]; td += sd[j]; }
        g_partD[(size_t)(nk * WW + w) * 2 + 0] = tn;
        g_partD[(size_t)(nk * WW + w) * 2 + 1] = td;
    }
}

// ---------------- K6: final ratio / loss ----------------
__global__ __launch_bounds__(256) void k_final(float* __restrict__ out) {
    int wid = threadIdx.x >> 5, lid = threadIdx.x & 31;  // wid = nk
    __shared__ float sr[8];
    {
        float num = 0.f, den = 0.f;
        for (int j = lid; j < WW; j += 32) {
            num += g_partD[(size_t)(wid * WW + j) * 2 + 0];
            den += g_partD[(size_t)(wid * WW + j) * 2 + 1];
        }
        #pragma unroll
        for (int o = 16; o > 0; o >>= 1) {
            num += __shfl_down_sync(0xffffffffu, num, o);
            den += __shfl_down_sync(0xffffffffu, den, o);
        }
        if (lid == 0) sr[wid] = fabsf(num / (den + 1e-6f));
    }
    __syncthreads();
    if (threadIdx.x == 0) {
        float loss = 0.f;
        #pragma unroll
        for (int k = 0; k < 4; k++)
            loss += 0.5f * (sr[k] + sr[4 + k]);
        out[0] = 4.0f - loss;
    }
}

extern "C" void kernel_launch(void* const* d_in, const int* in_sizes, int n_in,
                              void* d_out, int out_size) {
    const float* labels = (const float*)d_in[0];
    const float* inputs = (const float*)d_in[1];
    if (n_in >= 2 && in_sizes[0] < in_sizes[1]) {
        // be robust to input ordering: labels is the bigger tensor (4,096,000)
        const float* t = labels; labels = inputs; inputs = t;
    }
    float* out = (float*)d_out;

    k_sums <<<dim3(B1, NB), 256>>>(labels, inputs);
    k_means<<<1, 256>>>();
    k_convD<<<NK * HH, 256>>>(labels, inputs);
    k_convW<<<16 * HH, 256>>>();
    k_convH<<<NK * WW, 256>>>(labels);
    k_final<<<1, 256>>>(out);
}

// round 4
// speedup vs baseline: 2.4307x; 2.4307x over previous
#include <cuda_runtime.h>

#define NB   2
#define NK   8
#define VOX  512000
#define B1   128
#define CHUNK 4000

typedef unsigned long long u64;

// ---------------- packed f32x2 helpers ----------------
__device__ __forceinline__ u64 pack2(float lo, float hi) {
    u64 r; asm("mov.b64 %0,{%1,%2};" : "=l"(r) : "f"(lo), "f"(hi)); return r;
}
__device__ __forceinline__ float2 unpack2(u64 p) {
    float2 f; asm("mov.b64 {%0,%1},%2;" : "=f"(f.x), "=f"(f.y) : "l"(p)); return f;
}
__device__ __forceinline__ void fma2(u64 &a, u64 v, u64 c) {
    asm("fma.rn.f32x2 %0,%1,%2,%0;" : "+l"(a) : "l"(v), "l"(c));
}

// 11-tap unnormalized Gaussian, sigma=4: g[t] = exp(-(t-5)^2/32), symmetric
__device__ __forceinline__ void mk_taps(u64* t) {
    const float g[6] = { 0.45783335f, 0.60653066f, 0.75483960f,
                         0.88249690f, 0.96923321f, 1.00000000f };
    #pragma unroll
    for (int i = 0; i < 6; i++) t[i] = pack2(g[i], g[i]);
}

// Sliding-window 11-tap conv: L outputs, L+10 inputs, 1 load per input,
// ring of 11 packed accumulators. Fully unrolled so %11 folds.
template<int L, typename LoadF, typename EmitF>
__device__ __forceinline__ void slide11(const u64* taps, LoadF&& load, EmitF&& emit) {
    u64 acc[11];
    #pragma unroll
    for (int s = 0; s < 11; s++) acc[s] = 0ull;
    #pragma unroll
    for (int i = 0; i < L + 10; i++) {
        u64 v = load(i);
        #pragma unroll
        for (int j = 0; j <= 10; j++) {
            int o = i - 10 + j;              // tap t = 10-j, coeff g[t]
            if (o >= 0 && o < L) {
                int t = 10 - j;
                int u = (t <= 5) ? t : 10 - t;   // symmetry
                fma2(acc[o % 11], v, taps[u]);
            }
        }
        if (i >= 10) {
            emit(i - 10, acc[(i - 10) % 11]);
            acc[(i - 10) % 11] = 0ull;
        }
    }
}

// ---------------- scratch ----------------
__device__ float  g_part1[NB * B1 * 8];
__device__ float  g_mean[NK];
__device__ u64    g_bufA[NK * VOX];      // after exp + conv-W: (w,pw) packed, [nk][h][w][d]
__device__ float2 g_partC[NK * 80];      // per (nk,w) partial (num,den)

// ---------------- K1: partial sums for class means ----------------
__global__ __launch_bounds__(256) void k_sums(const float* __restrict__ labels,
                                              const float* __restrict__ inputs) {
    int n = blockIdx.y, b = blockIdx.x;
    int start = b * CHUNK, end = start + CHUNK;
    float a[8];
    #pragma unroll
    for (int j = 0; j < 8; j++) a[j] = 0.f;
    const float* ip = inputs + (size_t)n * VOX;
    for (int v = start + threadIdx.x; v < end; v += blockDim.x) {
        float iv = ip[v];
        #pragma unroll
        for (int k = 0; k < 4; k++) {
            float lv = labels[(size_t)(n * 4 + k) * VOX + v];
            a[k]     += lv;
            a[4 + k] += iv * lv;
        }
    }
    #pragma unroll
    for (int o = 16; o > 0; o >>= 1)
        #pragma unroll
        for (int j = 0; j < 8; j++)
            a[j] += __shfl_down_sync(0xffffffffu, a[j], o);
    __shared__ float s[8][8];
    int wid = threadIdx.x >> 5, lid = threadIdx.x & 31;
    if (lid == 0)
        #pragma unroll
        for (int j = 0; j < 8; j++) s[wid][j] = a[j];
    __syncthreads();
    if (threadIdx.x < 8) {
        int j = threadIdx.x;
        float acc = 0.f;
        #pragma unroll
        for (int w = 0; w < 8; w++) acc += s[w][j];
        g_part1[(size_t)(n * B1 + b) * 8 + j] = acc;
    }
}

// ---------------- K2: finish means ----------------
__global__ __launch_bounds__(256) void k_means() {
    int wid = threadIdx.x >> 5, lid = threadIdx.x & 31;   // wid = nk
    int n = wid >> 2, k = wid & 3;
    float sp = 0.f, sip = 0.f;
    for (int b = lid; b < B1; b += 32) {
        const float* p = g_part1 + (size_t)(n * B1 + b) * 8;
        sp  += p[k];
        sip += p[4 + k];
    }
    #pragma unroll
    for (int o = 16; o > 0; o >>= 1) {
        sp  += __shfl_down_sync(0xffffffffu, sp, o);
        sip += __shfl_down_sync(0xffffffffu, sip, o);
    }
    if (lid == 0) g_mean[wid] = sip / (sp + 5.12f);   // 1e-5 * 512000
}

// ---------------- KA: exp weights + conv along W (sliding, no smem) ----------------
// grid = NK*80 (nk,h); threads: 240 active = 80 d-lanes x 3 w-segments
__global__ __launch_bounds__(256) void kA(const float* __restrict__ labels,
                                          const float* __restrict__ inputs) {
    int bx = blockIdx.x;
    int nk = bx / 80, h = bx % 80, n = nk >> 2;
    float m = g_mean[nk];
    int tid = threadIdx.x;
    if (tid >= 240) return;
    int d = tid % 80, seg = tid / 80;
    u64 taps[6]; mk_taps(taps);
    const float* ip = inputs + (size_t)n  * VOX + (size_t)h * 6400 + d;
    const float* lp = labels + (size_t)nk * VOX + (size_t)h * 6400 + d;
    u64*         op = g_bufA + (size_t)nk * VOX + (size_t)h * 6400 + d;
    int w0 = seg * 27;
    auto load = [&](int i) -> u64 {
        int w = w0 - 5 + i;
        if (w < 0 || w >= 80) return 0ull;
        float iv = __ldg(ip + w * 80);
        float lv = __ldg(lp + w * 80);
        float t  = iv - m;
        float q  = t * t; q = q * q;
        float wv = __expf(-q);
        return pack2(wv, lv * wv);
    };
    auto emit = [&](int o, u64 a) { op[(w0 + o) * 80] = a; };
    if (seg < 2) slide11<27>(taps, load, emit);
    else         slide11<26>(taps, load, emit);
}

// ---------------- KB: conv-H (sliding -> smem) + conv-D (sliding over smem) + fused label reduce
// grid = NK*80 (nk,w); d handled in two overlapping chunks of 50 smem cols
__global__ __launch_bounds__(256) void kB(const float* __restrict__ labels) {
    int bx = blockIdx.x;
    int nk = bx / 80, w = bx % 80;
    int tid = threadIdx.x;
    __shared__ float sw[80 * 51];     // conv-H result, w channel, stride 51 (odd)
    __shared__ float spw[80 * 51];    // conv-H result, pw channel
    __shared__ float slab[80 * 41];   // labels for this (nk,w,chunk), stride 41 (odd)

    u64 taps[6]; mk_taps(taps);
    float num = 0.f, den = 0.f;

    const u64*   base  = g_bufA + (size_t)nk * VOX + (size_t)w * 80;
    const float* lbase = labels + (size_t)nk * VOX + (size_t)w * 80;

    for (int chunk = 0; chunk < 2; chunk++) {
        int cstart = chunk * 40;       // output d range [cstart, cstart+40)
        // zero pad columns: chunk0 -> j in [0,5) (d<0); chunk1 -> j in [45,50) (d>=80)
        for (int idx = tid; idx < 80 * 5; idx += 256) {
            int r = idx / 5, p = idx % 5;
            int j = (chunk == 0) ? p : 45 + p;
            sw[r * 51 + j]  = 0.f;
            spw[r * 51 + j] = 0.f;
        }
        // stage1: conv along H into smem; 225 threads = 45 d-cols x 5 h-segments of 16
        if (tid < 225) {
            int jv = tid % 45, hseg = tid / 45;
            int j  = (chunk == 0) ? jv + 5 : jv;     // smem col (covers d = cstart-5+j)
            int dg = (chunk == 0) ? jv     : 35 + jv; // global d
            int h0 = hseg * 16;
            const u64* cp = base + dg;
            auto load = [&](int i) -> u64 {
                int hh = h0 - 5 + i;
                return (hh < 0 || hh >= 80) ? 0ull : __ldg(cp + (size_t)hh * 6400);
            };
            auto emit = [&](int o, u64 a) {
                float2 f = unpack2(a);
                int r = h0 + o;
                sw[r * 51 + j]  = f.x;
                spw[r * 51 + j] = f.y;
            };
            slide11<16>(taps, load, emit);
        }
        // stage labels (coalesced)
        for (int idx = tid; idx < 80 * 40; idx += 256) {
            int r = idx / 40, dl = idx % 40;
            slab[r * 41 + dl] = __ldg(lbase + (size_t)r * 6400 + cstart + dl);
        }
        __syncthreads();
        // stage2: conv along D sliding over smem + label reduce
        // 240 threads = 80 h-rows x 3 d-segments (14,14,12)
        if (tid < 240) {
            int r = tid % 80, dseg = tid / 80;
            int d0 = dseg * 14;
            auto load = [&](int i) -> u64 {
                int j = d0 + i;                       // smem col for d = cstart+d0-5+i
                return pack2(sw[r * 51 + j], spw[r * 51 + j]);
            };
            auto emit = [&](int o, u64 a) {
                float2 f = unpack2(a);
                float lv = slab[r * 41 + d0 + o];
                den += lv * f.x;
                num += lv * f.y;
            };
            if (dseg < 2) slide11<14>(taps, load, emit);
            else          slide11<12>(taps, load, emit);
        }
        __syncthreads();
    }

    // block reduce num/den (inactive threads contribute 0)
    #pragma unroll
    for (int o = 16; o > 0; o >>= 1) {
        num += __shfl_down_sync(0xffffffffu, num, o);
        den += __shfl_down_sync(0xffffffffu, den, o);
    }
    __shared__ float sn[8], sd[8];
    int wid = tid >> 5, lid = tid & 31;
    if (lid == 0) { sn[wid] = num; sd[wid] = den; }
    __syncthreads();
    if (tid == 0) {
        float tn = 0.f, td = 0.f;
        #pragma unroll
        for (int j = 0; j < 8; j++) { tn += sn[j]; td += sd[j]; }
        g_partC[bx] = make_float2(tn, td);
    }
}

// ---------------- K final: ratio / loss ----------------
__global__ __launch_bounds__(256) void k_final(float* __restrict__ out) {
    int wid = threadIdx.x >> 5, lid = threadIdx.x & 31;   // wid = nk
    __shared__ float sr[8];
    {
        float num = 0.f, den = 0.f;
        for (int j = lid; j < 80; j += 32) {
            float2 p = g_partC[wid * 80 + j];
            num += p.x;
            den += p.y;
        }
        #pragma unroll
        for (int o = 16; o > 0; o >>= 1) {
            num += __shfl_down_sync(0xffffffffu, num, o);
            den += __shfl_down_sync(0xffffffffu, den, o);
        }
        if (lid == 0) sr[wid] = fabsf(num / (den + 1e-6f));
    }
    __syncthreads();
    if (threadIdx.x == 0) {
        float loss = 0.f;
        #pragma unroll
        for (int k = 0; k < 4; k++)
            loss += 0.5f * (sr[k] + sr[4 + k]);
        out[0] = 4.0f - loss;
    }
}

extern "C" void kernel_launch(void* const* d_in, const int* in_sizes, int n_in,
                              void* d_out, int out_size) {
    const float* labels = (const float*)d_in[0];
    const float* inputs = (const float*)d_in[1];
    if (n_in >= 2 && in_sizes[0] < in_sizes[1]) {
        const float* t = labels; labels = inputs; inputs = t;
    }
    float* out = (float*)d_out;

    k_sums <<<dim3(B1, NB), 256>>>(labels, inputs);
    k_means<<<1, 256>>>();
    kA     <<<NK * 80, 256>>>(labels, inputs);
    kB     <<<NK * 80, 256>>>(labels);
    k_final<<<1, 256>>>(out);
}